// round 5
// baseline (speedup 1.0000x reference)
#include <cuda_runtime.h>
#include <cuda_bf16.h>
#include <math.h>

// Last-block-finalize scratch. Zero-initialized at load; the finalizing block
// resets g_partial via atomicExch and the counter auto-wraps via atomicInc,
// so every graph replay sees identical initial state. No extra kernel needed.
__device__ float        g_partial;  // = 0
__device__ unsigned int g_count;    // = 0

__device__ __forceinline__ float4 ldcs4(const float4* p) {
    return __ldcs(p);
}

// Fused distance + mean reduction.
// R2's proven shape (unroll x4 = 8 front-batched LDG.128, 40 warps/SM) but at
// 128-thread CTA granularity (10 CTAs/SM) to halve the straggler quantum and
// smooth the kernel tail.
__global__ void __launch_bounds__(128, 10)
DIST_loss_49331994362453_kernel(const float4* __restrict__ preds,
                                const float4* __restrict__ targets,
                                float* __restrict__ out,
                                int n4, float inv_np1) {
    const int stride = gridDim.x * blockDim.x;
    int i = blockIdx.x * blockDim.x + threadIdx.x;

    float acc0 = 0.0f, acc1 = 0.0f, acc2 = 0.0f, acc3 = 0.0f;

    // Main unrolled loop: 8 independent 16B loads batched up front.
    for (; i + 3 * stride < n4; i += 4 * stride) {
        float4 a0 = ldcs4(preds   + i);
        float4 a1 = ldcs4(preds   + i + stride);
        float4 a2 = ldcs4(preds   + i + 2 * stride);
        float4 a3 = ldcs4(preds   + i + 3 * stride);
        float4 b0 = ldcs4(targets + i);
        float4 b1 = ldcs4(targets + i + stride);
        float4 b2 = ldcs4(targets + i + 2 * stride);
        float4 b3 = ldcs4(targets + i + 3 * stride);

        float dx, dy;
        dx = a0.x - b0.x; dy = a0.y - b0.y; acc0 += sqrtf(fmaf(dx, dx, dy * dy));
        dx = a0.z - b0.z; dy = a0.w - b0.w; acc0 += sqrtf(fmaf(dx, dx, dy * dy));
        dx = a1.x - b1.x; dy = a1.y - b1.y; acc1 += sqrtf(fmaf(dx, dx, dy * dy));
        dx = a1.z - b1.z; dy = a1.w - b1.w; acc1 += sqrtf(fmaf(dx, dx, dy * dy));
        dx = a2.x - b2.x; dy = a2.y - b2.y; acc2 += sqrtf(fmaf(dx, dx, dy * dy));
        dx = a2.z - b2.z; dy = a2.w - b2.w; acc2 += sqrtf(fmaf(dx, dx, dy * dy));
        dx = a3.x - b3.x; dy = a3.y - b3.y; acc3 += sqrtf(fmaf(dx, dx, dy * dy));
        dx = a3.z - b3.z; dy = a3.w - b3.w; acc3 += sqrtf(fmaf(dx, dx, dy * dy));
    }
    // Tail
    for (; i < n4; i += stride) {
        float4 a = ldcs4(preds + i);
        float4 b = ldcs4(targets + i);
        float dx, dy;
        dx = a.x - b.x; dy = a.y - b.y; acc0 += sqrtf(fmaf(dx, dx, dy * dy));
        dx = a.z - b.z; dy = a.w - b.w; acc0 += sqrtf(fmaf(dx, dx, dy * dy));
    }

    float acc = (acc0 + acc1) + (acc2 + acc3);

    // Warp reduction
    #pragma unroll
    for (int o = 16; o > 0; o >>= 1)
        acc += __shfl_down_sync(0xffffffffu, acc, o);

    __shared__ float warpsum[4];  // 128 threads = 4 warps
    const int lane = threadIdx.x & 31;
    const int wid  = threadIdx.x >> 5;
    if (lane == 0) warpsum[wid] = acc;
    __syncthreads();

    if (wid == 0) {
        acc = (lane < 4) ? warpsum[lane] : 0.0f;
        #pragma unroll
        for (int o = 2; o > 0; o >>= 1)
            acc += __shfl_down_sync(0xffffffffu, acc, o);

        if (lane == 0) {
            atomicAdd(&g_partial, acc);
            __threadfence();
            // atomicInc wraps to 0 at gridDim.x-1 -> counter self-resets.
            unsigned int ticket = atomicInc(&g_count, gridDim.x - 1);
            if (ticket == gridDim.x - 1) {
                // Last block: drain + self-reset accumulator, write result.
                float total = atomicExch(&g_partial, 0.0f);
                out[0] = total * inv_np1;
            }
        }
    }
}

extern "C" void kernel_launch(void* const* d_in, const int* in_sizes, int n_in,
                              void* d_out, int out_size) {
    const float4* preds   = (const float4*)d_in[0];
    const float4* targets = (const float4*)d_in[1];
    float* out = (float*)d_out;

    const int total_elems = in_sizes[0];      // N*2 floats
    const int n_points    = total_elems / 2;  // N
    const int n4          = total_elems / 4;  // float4 count (2 points each)
    const float inv_np1   = 1.0f / (float)(n_points + 1);

    const int threads = 128;
    int blocks = 148 * 10;  // one exact wave: 40 warps/SM at 10 CTAs/SM
    int max_needed = (n4 + threads - 1) / threads;
    if (blocks > max_needed) blocks = max_needed;

    DIST_loss_49331994362453_kernel<<<blocks, threads>>>(preds, targets, out,
                                                         n4, inv_np1);
}

// round 7
// speedup vs baseline: 1.0170x; 1.0170x over previous
#include <cuda_runtime.h>
#include <cuda_bf16.h>
#include <math.h>

// Last-block-finalize scratch. Zero-initialized at load; the finalizing block
// resets g_partial via atomicExch and the counter auto-wraps via atomicInc,
// so every graph replay sees identical initial state. No extra kernel needed.
__device__ float        g_partial;  // = 0
__device__ unsigned int g_count;    // = 0

__device__ __forceinline__ float4 ldcs4(const float4* p) {
    return __ldcs(p);
}

// Fused distance + mean reduction. R2's proven CTA shape (256 threads,
// unroll x4 = 8 front-batched LDG.128, occ 5 => 40 warps/SM) but launched as
// TWO waves (1480 CTAs) so early-finishing SMs steal wave-2 CTAs and the
// straggler tail halves.
__global__ void __launch_bounds__(256, 5)
DIST_loss_49331994362453_kernel(const float4* __restrict__ preds,
                                const float4* __restrict__ targets,
                                float* __restrict__ out,
                                int n4, float inv_np1) {
    const int stride = gridDim.x * blockDim.x;
    int i = blockIdx.x * blockDim.x + threadIdx.x;

    float acc0 = 0.0f, acc1 = 0.0f, acc2 = 0.0f, acc3 = 0.0f;

    // Main unrolled loop: 8 independent 16B loads batched up front.
    for (; i + 3 * stride < n4; i += 4 * stride) {
        float4 a0 = ldcs4(preds   + i);
        float4 a1 = ldcs4(preds   + i + stride);
        float4 a2 = ldcs4(preds   + i + 2 * stride);
        float4 a3 = ldcs4(preds   + i + 3 * stride);
        float4 b0 = ldcs4(targets + i);
        float4 b1 = ldcs4(targets + i + stride);
        float4 b2 = ldcs4(targets + i + 2 * stride);
        float4 b3 = ldcs4(targets + i + 3 * stride);

        float dx, dy;
        dx = a0.x - b0.x; dy = a0.y - b0.y; acc0 += sqrtf(fmaf(dx, dx, dy * dy));
        dx = a0.z - b0.z; dy = a0.w - b0.w; acc0 += sqrtf(fmaf(dx, dx, dy * dy));
        dx = a1.x - b1.x; dy = a1.y - b1.y; acc1 += sqrtf(fmaf(dx, dx, dy * dy));
        dx = a1.z - b1.z; dy = a1.w - b1.w; acc1 += sqrtf(fmaf(dx, dx, dy * dy));
        dx = a2.x - b2.x; dy = a2.y - b2.y; acc2 += sqrtf(fmaf(dx, dx, dy * dy));
        dx = a2.z - b2.z; dy = a2.w - b2.w; acc2 += sqrtf(fmaf(dx, dx, dy * dy));
        dx = a3.x - b3.x; dy = a3.y - b3.y; acc3 += sqrtf(fmaf(dx, dx, dy * dy));
        dx = a3.z - b3.z; dy = a3.w - b3.w; acc3 += sqrtf(fmaf(dx, dx, dy * dy));
    }
    // Tail
    for (; i < n4; i += stride) {
        float4 a = ldcs4(preds + i);
        float4 b = ldcs4(targets + i);
        float dx, dy;
        dx = a.x - b.x; dy = a.y - b.y; acc0 += sqrtf(fmaf(dx, dx, dy * dy));
        dx = a.z - b.z; dy = a.w - b.w; acc0 += sqrtf(fmaf(dx, dx, dy * dy));
    }

    float acc = (acc0 + acc1) + (acc2 + acc3);

    // Warp reduction
    #pragma unroll
    for (int o = 16; o > 0; o >>= 1)
        acc += __shfl_down_sync(0xffffffffu, acc, o);

    __shared__ float warpsum[8];  // 256 threads = 8 warps
    const int lane = threadIdx.x & 31;
    const int wid  = threadIdx.x >> 5;
    if (lane == 0) warpsum[wid] = acc;
    __syncthreads();

    if (wid == 0) {
        acc = (lane < 8) ? warpsum[lane] : 0.0f;
        #pragma unroll
        for (int o = 4; o > 0; o >>= 1)
            acc += __shfl_down_sync(0xffffffffu, acc, o);

        if (lane == 0) {
            atomicAdd(&g_partial, acc);
            __threadfence();
            // atomicInc wraps to 0 at gridDim.x-1 -> counter self-resets.
            unsigned int ticket = atomicInc(&g_count, gridDim.x - 1);
            if (ticket == gridDim.x - 1) {
                // Last block: drain + self-reset accumulator, write result.
                float total = atomicExch(&g_partial, 0.0f);
                out[0] = total * inv_np1;
            }
        }
    }
}

extern "C" void kernel_launch(void* const* d_in, const int* in_sizes, int n_in,
                              void* d_out, int out_size) {
    const float4* preds   = (const float4*)d_in[0];
    const float4* targets = (const float4*)d_in[1];
    float* out = (float*)d_out;

    const int total_elems = in_sizes[0];      // N*2 floats
    const int n_points    = total_elems / 2;  // N
    const int n4          = total_elems / 4;  // float4 count (2 points each)
    const float inv_np1   = 1.0f / (float)(n_points + 1);

    const int threads = 256;
    int blocks = 148 * 5 * 2;  // TWO waves at occupancy 5: work-steal smoothing
    int max_needed = (n4 + threads - 1) / threads;
    if (blocks > max_needed) blocks = max_needed;

    DIST_loss_49331994362453_kernel<<<blocks, threads>>>(preds, targets, out,
                                                         n4, inv_np1);
}

// round 10
// speedup vs baseline: 1.0552x; 1.0376x over previous
#include <cuda_runtime.h>
#include <cuda_bf16.h>
#include <math.h>

// Last-block-finalize scratch. Zero-initialized at load; the finalizing block
// resets g_partial via atomicExch and the counter auto-wraps via atomicInc,
// so every graph replay sees identical initial state. No extra kernel needed.
__device__ float        g_partial;  // = 0
__device__ unsigned int g_count;    // = 0

struct F8 { float v[8]; };

// 256-bit read-only global load (sm_100+). Falls back to two 128-bit loads.
__device__ __forceinline__ F8 ldg256(const float* p) {
    F8 r;
#if defined(__CUDA_ARCH__) && (__CUDA_ARCH__ >= 1000)
    asm volatile("ld.global.nc.v8.f32 {%0,%1,%2,%3,%4,%5,%6,%7}, [%8];"
                 : "=f"(r.v[0]), "=f"(r.v[1]), "=f"(r.v[2]), "=f"(r.v[3]),
                   "=f"(r.v[4]), "=f"(r.v[5]), "=f"(r.v[6]), "=f"(r.v[7])
                 : "l"(p));
#else
    float4 a = __ldcs((const float4*)p);
    float4 b = __ldcs((const float4*)p + 1);
    r.v[0] = a.x; r.v[1] = a.y; r.v[2] = a.z; r.v[3] = a.w;
    r.v[4] = b.x; r.v[5] = b.y; r.v[6] = b.z; r.v[7] = b.w;
#endif
    return r;
}

// Fused distance + mean reduction. Proven R2 shape (256 threads, occ 5,
// 740 blocks = one wave, 8 front-batched lines per thread) but with 256-bit
// loads: 4 LDG.256 per loop body instead of 8 LDG.128 — same bytes, half the
// issue slots and L1tex queue entries.
__global__ void __launch_bounds__(256, 5)
DIST_loss_49331994362453_kernel(const float* __restrict__ preds,
                                const float* __restrict__ targets,
                                float* __restrict__ out,
                                int n8, float inv_np1) {
    // n8 = number of 8-float (4-point) groups. Index unit below: one F8 group.
    const int stride = gridDim.x * blockDim.x;
    int i = blockIdx.x * blockDim.x + threadIdx.x;

    float acc0 = 0.0f, acc1 = 0.0f, acc2 = 0.0f, acc3 = 0.0f;

    // Main loop: unroll x2 of F8 groups = 4 x LDG.256 front-batched
    // (8 x 128B lines per thread in flight, matching R2's MLP).
    for (; i + stride < n8; i += 2 * stride) {
        F8 a0 = ldg256(preds   + (size_t)i * 8);
        F8 a1 = ldg256(preds   + (size_t)(i + stride) * 8);
        F8 b0 = ldg256(targets + (size_t)i * 8);
        F8 b1 = ldg256(targets + (size_t)(i + stride) * 8);

        float dx, dy;
        dx = a0.v[0] - b0.v[0]; dy = a0.v[1] - b0.v[1]; acc0 += sqrtf(fmaf(dx, dx, dy * dy));
        dx = a0.v[2] - b0.v[2]; dy = a0.v[3] - b0.v[3]; acc1 += sqrtf(fmaf(dx, dx, dy * dy));
        dx = a0.v[4] - b0.v[4]; dy = a0.v[5] - b0.v[5]; acc2 += sqrtf(fmaf(dx, dx, dy * dy));
        dx = a0.v[6] - b0.v[6]; dy = a0.v[7] - b0.v[7]; acc3 += sqrtf(fmaf(dx, dx, dy * dy));
        dx = a1.v[0] - b1.v[0]; dy = a1.v[1] - b1.v[1]; acc0 += sqrtf(fmaf(dx, dx, dy * dy));
        dx = a1.v[2] - b1.v[2]; dy = a1.v[3] - b1.v[3]; acc1 += sqrtf(fmaf(dx, dx, dy * dy));
        dx = a1.v[4] - b1.v[4]; dy = a1.v[5] - b1.v[5]; acc2 += sqrtf(fmaf(dx, dx, dy * dy));
        dx = a1.v[6] - b1.v[6]; dy = a1.v[7] - b1.v[7]; acc3 += sqrtf(fmaf(dx, dx, dy * dy));
    }
    // Tail
    for (; i < n8; i += stride) {
        F8 a = ldg256(preds   + (size_t)i * 8);
        F8 b = ldg256(targets + (size_t)i * 8);
        float dx, dy;
        dx = a.v[0] - b.v[0]; dy = a.v[1] - b.v[1]; acc0 += sqrtf(fmaf(dx, dx, dy * dy));
        dx = a.v[2] - b.v[2]; dy = a.v[3] - b.v[3]; acc1 += sqrtf(fmaf(dx, dx, dy * dy));
        dx = a.v[4] - b.v[4]; dy = a.v[5] - b.v[5]; acc2 += sqrtf(fmaf(dx, dx, dy * dy));
        dx = a.v[6] - b.v[6]; dy = a.v[7] - b.v[7]; acc3 += sqrtf(fmaf(dx, dx, dy * dy));
    }

    float acc = (acc0 + acc1) + (acc2 + acc3);

    // Warp reduction
    #pragma unroll
    for (int o = 16; o > 0; o >>= 1)
        acc += __shfl_down_sync(0xffffffffu, acc, o);

    __shared__ float warpsum[8];  // 256 threads = 8 warps
    const int lane = threadIdx.x & 31;
    const int wid  = threadIdx.x >> 5;
    if (lane == 0) warpsum[wid] = acc;
    __syncthreads();

    if (wid == 0) {
        acc = (lane < 8) ? warpsum[lane] : 0.0f;
        #pragma unroll
        for (int o = 4; o > 0; o >>= 1)
            acc += __shfl_down_sync(0xffffffffu, acc, o);

        if (lane == 0) {
            atomicAdd(&g_partial, acc);
            __threadfence();
            // atomicInc wraps to 0 at gridDim.x-1 -> counter self-resets.
            unsigned int ticket = atomicInc(&g_count, gridDim.x - 1);
            if (ticket == gridDim.x - 1) {
                // Last block: drain + self-reset accumulator, write result.
                float total = atomicExch(&g_partial, 0.0f);
                out[0] = total * inv_np1;
            }
        }
    }
}

extern "C" void kernel_launch(void* const* d_in, const int* in_sizes, int n_in,
                              void* d_out, int out_size) {
    const float* preds   = (const float*)d_in[0];
    const float* targets = (const float*)d_in[1];
    float* out = (float*)d_out;

    const int total_elems = in_sizes[0];      // N*2 floats (N=16777216 -> 33554432)
    const int n_points    = total_elems / 2;  // N
    const int n8          = total_elems / 8;  // 8-float groups (4 points each)
    const float inv_np1   = 1.0f / (float)(n_points + 1);

    const int threads = 256;
    int blocks = 148 * 5;  // one exact wave at occupancy 5 (R2's proven grid)
    int max_needed = (n8 + threads - 1) / threads;
    if (blocks > max_needed) blocks = max_needed;

    DIST_loss_49331994362453_kernel<<<blocks, threads>>>(preds, targets, out,
                                                         n8, inv_np1);
}